// round 12
// baseline (speedup 1.0000x reference)
#include <cuda_runtime.h>
#include <cuda_fp16.h>
#include <math.h>

#define B_   32
#define T_   256
#define I_   512
#define C_   512
#define G_   2048
#define NB_  8
#define KK_  4096          // NB_*C_ flattened recurrent K
#define LOSC 2048.0f
#define LOIN (1.0f/2048.0f)

// ---------------- scratch ----------------
__device__ float  g_cb[B_ * NB_];
__device__ int    g_len[B_];
__device__ float  g_bmix[2 * B_ * G_];
__device__ float  g_WihMix[2UL * B_ * G_ * I_];
__device__ float  g_gatesx[2UL * B_ * T_ * G_];      // x@Wih + bias
__device__ __half g_Whi[2UL * G_ * KK_];             // [d][g][n*512+k] hi
__device__ __half g_Wlo[2UL * G_ * KK_];             // lo * 2^11
__device__ __half g_Ah[2UL * 2 * B_ * KK_];          // H~ hi [parity][d][b][nk]
__device__ __half g_Al[2UL * 2 * B_ * KK_];          // H~ lo * 2^11
__device__ float  g_cst[2 * B_ * C_];                // c state [d][b][cell]

// ---------------- K1: lengths + c_batch ----------------
__global__ void k_prep(const void* __restrict__ mask_raw,
                       const int* __restrict__ ma, const int* __restrict__ mc,
                       const float* __restrict__ EA, const float* __restrict__ EC,
                       const float* __restrict__ W1, const float* __restrict__ b1,
                       const float* __restrict__ W2)
{
    __shared__ float q[128], hid[64], lg[8];
    int b = blockIdx.x, lane = threadIdx.x;
    int w0 = ((const int*)mask_raw)[0];
    int mode = (w0 == 1) ? 1 : ((w0 == 0x3F800000) ? 2 : 0);
    int s = 0;
    if (mode == 1) { const int* m = (const int*)mask_raw;
        for (int t = lane; t < T_; t += 32) s += (m[b*T_+t] != 0);
    } else if (mode == 2) { const float* m = (const float*)mask_raw;
        for (int t = lane; t < T_; t += 32) s += (m[b*T_+t] != 0.0f);
    } else { const unsigned char* m = (const unsigned char*)mask_raw;
        for (int t = lane; t < T_; t += 32) s += (m[b*T_+t] != 0);
    }
    #pragma unroll
    for (int o = 16; o; o >>= 1) s += __shfl_xor_sync(0xffffffffu, s, o);
    if (lane == 0) g_len[b] = s;

    int a = ma[b], c = mc[b];
    #pragma unroll
    for (int u = 0; u < 4; u++) {
        int i = lane*4 + u;
        q[i] = (i < 64) ? EA[a*64 + i] : EC[c*64 + (i-64)];
    }
    __syncwarp();
    for (int j = lane; j < 64; j += 32) {
        float acc = b1[j];
        for (int i = 0; i < 128; i++) acc += q[i] * W1[i*64 + j];
        hid[j] = tanhf(acc);
    }
    __syncwarp();
    if (lane < 8) {
        float acc = 0.f;
        for (int j = 0; j < 64; j++) acc += hid[j] * W2[j*8 + lane];
        lg[lane] = acc;
    }
    __syncwarp();
    if (lane < 8) {
        float m = lg[0];
        #pragma unroll
        for (int n = 1; n < 8; n++) m = fmaxf(m, lg[n]);
        float Z = 0.f;
        #pragma unroll
        for (int n = 0; n < 8; n++) Z += expf(lg[n] - m);
        g_cb[b*8 + lane] = expf(lg[lane] - m) / Z;
    }
}

// ---------------- K2: zero A (both parities) + c state ----------------
__global__ void k_init()
{
    int i = blockIdx.x * 256 + threadIdx.x;
    ((unsigned int*)g_Ah)[i] = 0u;
    ((unsigned int*)g_Al)[i] = 0u;
    if (i < 2 * B_ * C_) g_cst[i] = 0.f;
}

// ---------------- K3: mixed bias ----------------
__global__ void k_mixbias(const float* __restrict__ bf, const float* __restrict__ br)
{
    int idx = blockIdx.x * 256 + threadIdx.x;
    int g = idx & (G_-1), b = (idx >> 11) & 31, d = idx >> 16;
    const float* bias = d ? br : bf;
    float acc = 0.f;
    #pragma unroll
    for (int n = 0; n < NB_; n++) acc += g_cb[b*8+n] * bias[n*G_ + g];
    g_bmix[idx] = acc;
}

// ---------------- K4: mix input weights ----------------
__global__ void k_mix_ih(const float* __restrict__ Wf, const float* __restrict__ Wr)
{
    __shared__ float cbs[256];
    int tid = threadIdx.x;
    cbs[tid] = g_cb[tid];
    __syncthreads();
    int idx = blockIdx.x * 256 + tid;
    int k4 = idx & 127, g = (idx >> 7) & (G_-1), d = idx >> 18;
    const float* W = d ? Wr : Wf;
    float4 w[NB_];
    #pragma unroll
    for (int n = 0; n < NB_; n++)
        w[n] = *(const float4*)&W[((size_t)n*G_ + g)*I_ + k4*4];
    for (int b = 0; b < B_; b++) {
        float4 o = make_float4(0.f,0.f,0.f,0.f);
        #pragma unroll
        for (int n = 0; n < NB_; n++) {
            float c = cbs[b*8+n];
            o.x += c*w[n].x; o.y += c*w[n].y; o.z += c*w[n].z; o.w += c*w[n].w;
        }
        *(float4*)&g_WihMix[((size_t)(d*B_+b)*G_ + g)*I_ + k4*4] = o;
    }
}

// ---------------- K5: basis Whh -> fp16 hi/lo, layout [d][g][n*512+k] ----------------
__global__ void k_wcvt(const float* __restrict__ Wf, const float* __restrict__ Wr)
{
    int idx = blockIdx.x * 256 + threadIdx.x;
    int k8 = idx & 63, n = (idx >> 6) & 7, g = (idx >> 9) & 2047, d = idx >> 20;
    const float* W = d ? Wr : Wf;
    const float* src = &W[((size_t)n*G_ + g)*C_ + k8*8];
    float4 v0 = *(const float4*)src;
    float4 v1 = *(const float4*)(src + 4);
    float vs[8] = {v0.x,v0.y,v0.z,v0.w, v1.x,v1.y,v1.z,v1.w};
    __half h8[8], l8[8];
    #pragma unroll
    for (int i = 0; i < 8; i++) {
        __half h = __float2half(vs[i]);
        h8[i] = h;
        l8[i] = __float2half((vs[i] - __half2float(h)) * LOSC);
    }
    size_t dst = (size_t)(d*G_ + g)*KK_ + n*C_ + k8*8;
    *(uint4*)(g_Whi + dst) = *(uint4*)h8;
    *(uint4*)(g_Wlo + dst) = *(uint4*)l8;
}

// ---------------- K6: input GEMM + bias fold ----------------
__global__ void __launch_bounds__(256, 2) k_ingemm(const float* __restrict__ x)
{
    __shared__ float As[16][132];
    __shared__ float Bs[16][132];
    int tid = threadIdx.x;
    int gt = blockIdx.x & 15, tt = (blockIdx.x >> 4) & 1;
    int b = (blockIdx.x >> 5) & 31, d = blockIdx.x >> 10;
    int t0 = tt*128, g0 = gt*128;
    const float* A  = &x[(size_t)b * T_ * I_];
    const float* Bw = &g_WihMix[(size_t)(d*B_+b) * G_ * I_];
    float acc[8][8];
    #pragma unroll
    for (int i = 0; i < 8; i++)
        #pragma unroll
        for (int j = 0; j < 8; j++) acc[i][j] = 0.f;
    int tx = tid & 15, ty = tid >> 4;
    for (int kc = 0; kc < I_; kc += 16) {
        #pragma unroll
        for (int u = 0; u < 2; u++) {
            int e = tid + u*256, row = e >> 2, c4 = e & 3;
            float4 v = *(const float4*)&A[(size_t)(t0+row)*I_ + kc + c4*4];
            As[c4*4+0][row]=v.x; As[c4*4+1][row]=v.y; As[c4*4+2][row]=v.z; As[c4*4+3][row]=v.w;
            float4 w = *(const float4*)&Bw[(size_t)(g0+row)*I_ + kc + c4*4];
            Bs[c4*4+0][row]=w.x; Bs[c4*4+1][row]=w.y; Bs[c4*4+2][row]=w.z; Bs[c4*4+3][row]=w.w;
        }
        __syncthreads();
        #pragma unroll
        for (int kk = 0; kk < 16; kk++) {
            float4 a0 = *(float4*)&As[kk][tx*8];
            float4 a1 = *(float4*)&As[kk][tx*8+4];
            float4 b0 = *(float4*)&Bs[kk][ty*8];
            float4 b1 = *(float4*)&Bs[kk][ty*8+4];
            float av[8] = {a0.x,a0.y,a0.z,a0.w,a1.x,a1.y,a1.z,a1.w};
            float bv[8] = {b0.x,b0.y,b0.z,b0.w,b1.x,b1.y,b1.z,b1.w};
            #pragma unroll
            for (int i = 0; i < 8; i++)
                #pragma unroll
                for (int j = 0; j < 8; j++) acc[i][j] += av[i]*bv[j];
        }
        __syncthreads();
    }
    const float* bm = &g_bmix[((d*B_+b) << 11) + g0 + ty*8];
    float bj[8];
    #pragma unroll
    for (int j = 0; j < 8; j++) bj[j] = bm[j];
    float* O = &g_gatesx[(size_t)(d*B_+b) * T_ * G_];
    #pragma unroll
    for (int i = 0; i < 8; i++) {
        int t = t0 + tx*8 + i;
        #pragma unroll
        for (int j = 0; j < 8; j += 4) {
            float4 v = make_float4(acc[i][j]+bj[j], acc[i][j+1]+bj[j+1],
                                   acc[i][j+2]+bj[j+2], acc[i][j+3]+bj[j+3]);
            *(float4*)&O[(size_t)t*G_ + g0 + ty*8 + j] = v;
        }
    }
}

// ---------------- K7: tensor-core recurrent step (4-stage, K-chunk=128) ----------------
#define CP16(dst, src) asm volatile("cp.async.ca.shared.global [%0], [%1], 16;\n"::"r"(dst),"l"(src):"memory")
#define LDX4(r0,r1,r2,r3,ad) asm volatile("ldmatrix.sync.aligned.m8n8.x4.shared.b16 {%0,%1,%2,%3}, [%4];":"=r"(r0),"=r"(r1),"=r"(r2),"=r"(r3):"r"(ad))
#define LDX2(r0,r1,ad) asm volatile("ldmatrix.sync.aligned.m8n8.x2.shared.b16 {%0,%1}, [%2];":"=r"(r0),"=r"(r1):"r"(ad))
#define MMA16(cc,a0,a1,a2,a3,b0,b1) asm volatile( \
    "mma.sync.aligned.m16n8k16.row.col.f32.f16.f16.f32 {%0,%1,%2,%3},{%4,%5,%6,%7},{%8,%9},{%0,%1,%2,%3};" \
    :"+f"(cc[0]),"+f"(cc[1]),"+f"(cc[2]),"+f"(cc[3]) \
    :"r"(a0),"r"(a1),"r"(a2),"r"(a3),"r"(b0),"r"(b1))

// Stage layout (32KB): Ah[32][128] | Al[32][128] | Wh[32][128] | Wl[32][128]
// rows of 128 half = 256B = 16 granules of 16B; swizzle granule g -> g ^ (row&7)
#define STG_ 32768u
#define NCH_ 32

__global__ void __launch_bounds__(256, 1) k_step(int s, float* __restrict__ out)
{
    extern __shared__ __align__(1024) __half smd[];    // 4 stages x 32KB
    const int tid = threadIdx.x;
    const int d  = blockIdx.x >> 6;
    const int c0 = (blockIdx.x & 63) * 8;
    const int p  = s & 1;
    const int t  = d ? (T_-1-s) : s;
    const unsigned smb = (unsigned)__cvta_generic_to_shared(smd);

    // --- producer mapping: tile = tid>>6 (Ah,Al,Wh,Wl), 8 x 16B lines / thread ---
    const int ldt  = tid >> 6;
    const int lsub = tid & 63;
    const int lrow = lsub >> 1;          // 0..31
    const int li   = (lsub & 1) * 8;     // granule start 0 or 8
    const __half* gb;
    if (ldt == 0)      gb = g_Ah + ((size_t)((p*2+d)*B_ + lrow))*KK_;
    else if (ldt == 1) gb = g_Al + ((size_t)((p*2+d)*B_ + lrow))*KK_;
    else {
        int grow = (lrow >> 3)*512 + c0 + (lrow & 7);
        gb = ((ldt == 2) ? g_Whi : g_Wlo) + ((size_t)(d*G_ + grow))*KK_;
    }
    const int r7 = lrow & 7;
    const unsigned dstb = smb + ldt*8192 + lrow*256;

#define ISSUE(c) { unsigned so = ((unsigned)(c) & 3u) * STG_; const __half* gp = gb + (size_t)(c)*128 + li*8; \
    _Pragma("unroll") for (int j = 0; j < 8; j++) CP16(dstb + so + ((unsigned)((li+j) ^ r7) << 4), gp + j*8); \
    asm volatile("cp.async.commit_group;\n":::"memory"); }

    // --- consumer mapping: 8 warps = 2 m-halves x 4 gates ---
    const int lane = tid & 31, wid = tid >> 5;
    const int mh = wid & 1, q = wid >> 1;
    const int rowA = mh*16 + (lane & 15), cgA = lane >> 4;
    const int rowB = q*8 + (lane & 7),  cgB = (lane >> 3) & 1;
    const int rA7 = rowA & 7, rB7 = rowB & 7;
    const unsigned baseA = smb + rowA*256;
    const unsigned baseB = smb + 16384u + rowB*256;
    float aM[4] = {0.f,0.f,0.f,0.f};
    float aL[4] = {0.f,0.f,0.f,0.f};

    ISSUE(0); ISSUE(1); ISSUE(2);
    for (int c = 0; c < NCH_; c++) {
        asm volatile("cp.async.wait_group 2;\n":::"memory");
        __syncthreads();
        if (c + 3 < NCH_) { ISSUE(c + 3); }
        else { asm volatile("cp.async.commit_group;\n":::"memory"); }
        unsigned st = ((unsigned)c & 3u) * STG_;
        #pragma unroll
        for (int ks = 0; ks < 8; ks++) {
            unsigned offA = baseA + st + ((unsigned)((ks*2+cgA) ^ rA7) << 4);
            unsigned offB = baseB + st + ((unsigned)((ks*2+cgB) ^ rB7) << 4);
            unsigned ah0,ah1,ah2,ah3, al0,al1,al2,al3, bh0,bh1, bl0,bl1;
            LDX4(ah0,ah1,ah2,ah3, offA);
            LDX4(al0,al1,al2,al3, offA + 8192u);
            LDX2(bh0,bh1, offB);
            LDX2(bl0,bl1, offB + 8192u);
            MMA16(aM, ah0,ah1,ah2,ah3, bh0,bh1);
            MMA16(aL, ah0,ah1,ah2,ah3, bl0,bl1);
            MMA16(aL, al0,al1,al2,al3, bh0,bh1);
        }
    }
    __syncthreads();

    // --- stage gates to smem (overlay stage memory) ---
    float* gsm = (float*)smd;                       // [4 gates][32 b][8 cells]
    {
        int r0 = mh*16 + (lane >> 2);
        int cn = (lane & 3) * 2;
        gsm[q*256 + r0*8     + cn    ] = aM[0] + aL[0]*LOIN;
        gsm[q*256 + r0*8     + cn + 1] = aM[1] + aL[1]*LOIN;
        gsm[q*256 + (r0+8)*8 + cn    ] = aM[2] + aL[2]*LOIN;
        gsm[q*256 + (r0+8)*8 + cn + 1] = aM[3] + aL[3]*LOIN;
    }
    __syncthreads();

    // --- LSTM pointwise + next-step H~ staging ---
    {
        int b = tid >> 3, ce = tid & 7;
        const float* gx = g_gatesx + ((size_t)(d*B_+b)*T_ + t)*G_ + c0 + ce;
        float gi = gsm[       b*8 + ce] + gx[0];
        float gf = gsm[256  + b*8 + ce] + gx[512];
        float gg = gsm[512  + b*8 + ce] + gx[1024];
        float go = gsm[768  + b*8 + ce] + gx[1536];
        int cell = c0 + ce;
        float cprev = g_cst[(d*B_+b)*C_ + cell];
        float i_ = 1.f / (1.f + expf(-gi));
        float f_ = 1.f / (1.f + expf(-gf));
        float g2 = tanhf(gg);
        float o_ = 1.f / (1.f + expf(-go));
        float cy = f_*cprev + i_*g2;
        float hy = o_*tanhf(cy);
        int len = g_len[b];
        bool valid = d ? ((T_ - s) <= len) : (s < len);
        if (!valid) { cy = 0.f; hy = 0.f; }
        g_cst[(d*B_+b)*C_ + cell] = cy;
        out[((size_t)b*T_ + t)*(2*C_) + d*C_ + cell] = hy;
        int pn = p ^ 1;
        size_t ab = ((size_t)((pn*2+d)*B_ + b))*KK_ + cell;
        #pragma unroll
        for (int n = 0; n < 8; n++) {
            float af = g_cb[b*8+n] * hy;
            __half h = __float2half(af);
            g_Ah[ab + n*512] = h;
            g_Al[ab + n*512] = __float2half((af - __half2float(h)) * LOSC);
        }
    }
}

// ---------------- launcher ----------------
extern "C" void kernel_launch(void* const* d_in, const int* in_sizes, int n_in,
                              void* d_out, int out_size)
{
    const float* x    = (const float*)d_in[0];
    const void*  mask = (const void*)d_in[1];
    const int*   ma   = (const int*)d_in[2];
    const int*   mc   = (const int*)d_in[3];
    const float* EA   = (const float*)d_in[4];
    const float* EC   = (const float*)d_in[5];
    const float* W1   = (const float*)d_in[6];
    const float* b1   = (const float*)d_in[7];
    const float* W2   = (const float*)d_in[8];
    const float* Wih  = (const float*)d_in[9];
    const float* Whh  = (const float*)d_in[10];
    const float* bias = (const float*)d_in[11];
    const float* WihR = (const float*)d_in[12];
    const float* WhhR = (const float*)d_in[13];
    const float* biasR= (const float*)d_in[14];
    float*       out  = (float*)d_out;

    static int s_attr_done = 0;
    if (!s_attr_done) {
        cudaFuncSetAttribute(k_step, cudaFuncAttributeMaxDynamicSharedMemorySize, 4 * 32768);
        s_attr_done = 1;
    }

    k_prep   <<<B_, 32>>>(mask, ma, mc, EA, EC, W1, b1, W2);
    k_init   <<<1024, 256>>>();
    k_mixbias<<<512, 256>>>(bias, biasR);
    k_mix_ih <<<2048, 256>>>(Wih, WihR);
    k_wcvt   <<<8192, 256>>>(Whh, WhhR);
    k_ingemm <<<2048, 256>>>(x);
    for (int s = 0; s < T_; s++)
        k_step<<<128, 256, 4 * 32768>>>(s, out);
}

// round 16
// speedup vs baseline: 1.5775x; 1.5775x over previous
#include <cuda_runtime.h>
#include <cuda_fp16.h>
#include <math.h>

#define B_   32
#define T_   256
#define I_   512
#define C_   512
#define G_   2048
#define NB_  8
#define KK_  4096
#define LOSC 2048.0f
#define LOIN (1.0f/2048.0f)
#define GRID_STEP 128

// ---------------- scratch ----------------
__device__ float  g_cb[B_ * NB_];
__device__ int    g_len[B_];
__device__ float  g_bmix[2 * B_ * G_];
__device__ float  g_WihMix[2UL * B_ * G_ * I_];
__device__ float  g_gatesx[2UL * B_ * T_ * G_];
__device__ __half g_Whi[2UL * G_ * KK_];             // [d][g][n*512+k] hi
__device__ __half g_Wlo[2UL * G_ * KK_];             // lo * 2^11
__device__ __half g_Ah[2UL * 2 * B_ * KK_];          // H~ hi [parity][d][b][nk]
__device__ __half g_Al[2UL * 2 * B_ * KK_];          // H~ lo * 2^11
__device__ float  g_cst[2 * B_ * C_];
__device__ int    g_bar;

// ---------------- K1: lengths + c_batch ----------------
__global__ void k_prep(const void* __restrict__ mask_raw,
                       const int* __restrict__ ma, const int* __restrict__ mc,
                       const float* __restrict__ EA, const float* __restrict__ EC,
                       const float* __restrict__ W1, const float* __restrict__ b1,
                       const float* __restrict__ W2)
{
    __shared__ float q[128], hid[64], lg[8];
    int b = blockIdx.x, lane = threadIdx.x;
    int w0 = ((const int*)mask_raw)[0];
    int mode = (w0 == 1) ? 1 : ((w0 == 0x3F800000) ? 2 : 0);
    int s = 0;
    if (mode == 1) { const int* m = (const int*)mask_raw;
        for (int t = lane; t < T_; t += 32) s += (m[b*T_+t] != 0);
    } else if (mode == 2) { const float* m = (const float*)mask_raw;
        for (int t = lane; t < T_; t += 32) s += (m[b*T_+t] != 0.0f);
    } else { const unsigned char* m = (const unsigned char*)mask_raw;
        for (int t = lane; t < T_; t += 32) s += (m[b*T_+t] != 0);
    }
    #pragma unroll
    for (int o = 16; o; o >>= 1) s += __shfl_xor_sync(0xffffffffu, s, o);
    if (lane == 0) g_len[b] = s;

    int a = ma[b], c = mc[b];
    #pragma unroll
    for (int u = 0; u < 4; u++) {
        int i = lane*4 + u;
        q[i] = (i < 64) ? EA[a*64 + i] : EC[c*64 + (i-64)];
    }
    __syncwarp();
    for (int j = lane; j < 64; j += 32) {
        float acc = b1[j];
        for (int i = 0; i < 128; i++) acc += q[i] * W1[i*64 + j];
        hid[j] = tanhf(acc);
    }
    __syncwarp();
    if (lane < 8) {
        float acc = 0.f;
        for (int j = 0; j < 64; j++) acc += hid[j] * W2[j*8 + lane];
        lg[lane] = acc;
    }
    __syncwarp();
    if (lane < 8) {
        float m = lg[0];
        #pragma unroll
        for (int n = 1; n < 8; n++) m = fmaxf(m, lg[n]);
        float Z = 0.f;
        #pragma unroll
        for (int n = 0; n < 8; n++) Z += expf(lg[n] - m);
        g_cb[b*8 + lane] = expf(lg[lane] - m) / Z;
    }
}

// ---------------- K2: zero A (both parities) + c state + barrier ----------------
__global__ void k_init()
{
    int i = blockIdx.x * 256 + threadIdx.x;
    ((unsigned int*)g_Ah)[i] = 0u;
    ((unsigned int*)g_Al)[i] = 0u;
    if (i < 2 * B_ * C_) g_cst[i] = 0.f;
    if (i == 0) g_bar = 0;
}

// ---------------- K3: mixed bias ----------------
__global__ void k_mixbias(const float* __restrict__ bf, const float* __restrict__ br)
{
    int idx = blockIdx.x * 256 + threadIdx.x;
    int g = idx & (G_-1), b = (idx >> 11) & 31, d = idx >> 16;
    const float* bias = d ? br : bf;
    float acc = 0.f;
    #pragma unroll
    for (int n = 0; n < NB_; n++) acc += g_cb[b*8+n] * bias[n*G_ + g];
    g_bmix[idx] = acc;
}

// ---------------- K4: mix input weights ----------------
__global__ void k_mix_ih(const float* __restrict__ Wf, const float* __restrict__ Wr)
{
    __shared__ float cbs[256];
    int tid = threadIdx.x;
    cbs[tid] = g_cb[tid];
    __syncthreads();
    int idx = blockIdx.x * 256 + tid;
    int k4 = idx & 127, g = (idx >> 7) & (G_-1), d = idx >> 18;
    const float* W = d ? Wr : Wf;
    float4 w[NB_];
    #pragma unroll
    for (int n = 0; n < NB_; n++)
        w[n] = *(const float4*)&W[((size_t)n*G_ + g)*I_ + k4*4];
    for (int b = 0; b < B_; b++) {
        float4 o = make_float4(0.f,0.f,0.f,0.f);
        #pragma unroll
        for (int n = 0; n < NB_; n++) {
            float c = cbs[b*8+n];
            o.x += c*w[n].x; o.y += c*w[n].y; o.z += c*w[n].z; o.w += c*w[n].w;
        }
        *(float4*)&g_WihMix[((size_t)(d*B_+b)*G_ + g)*I_ + k4*4] = o;
    }
}

// ---------------- K5: basis Whh -> fp16 hi/lo, layout [d][g][n*512+k] ----------------
__global__ void k_wcvt(const float* __restrict__ Wf, const float* __restrict__ Wr)
{
    int idx = blockIdx.x * 256 + threadIdx.x;
    int k8 = idx & 63, n = (idx >> 6) & 7, g = (idx >> 9) & 2047, d = idx >> 20;
    const float* W = d ? Wr : Wf;
    const float* src = &W[((size_t)n*G_ + g)*C_ + k8*8];
    float4 v0 = *(const float4*)src;
    float4 v1 = *(const float4*)(src + 4);
    float vs[8] = {v0.x,v0.y,v0.z,v0.w, v1.x,v1.y,v1.z,v1.w};
    __half h8[8], l8[8];
    #pragma unroll
    for (int i = 0; i < 8; i++) {
        __half h = __float2half(vs[i]);
        h8[i] = h;
        l8[i] = __float2half((vs[i] - __half2float(h)) * LOSC);
    }
    size_t dst = (size_t)(d*G_ + g)*KK_ + n*C_ + k8*8;
    *(uint4*)(g_Whi + dst) = *(uint4*)h8;
    *(uint4*)(g_Wlo + dst) = *(uint4*)l8;
}

// ---------------- K6: input GEMM + bias fold ----------------
__global__ void __launch_bounds__(256, 2) k_ingemm(const float* __restrict__ x)
{
    __shared__ float As[16][132];
    __shared__ float Bs[16][132];
    int tid = threadIdx.x;
    int gt = blockIdx.x & 15, tt = (blockIdx.x >> 4) & 1;
    int b = (blockIdx.x >> 5) & 31, d = blockIdx.x >> 10;
    int t0 = tt*128, g0 = gt*128;
    const float* A  = &x[(size_t)b * T_ * I_];
    const float* Bw = &g_WihMix[(size_t)(d*B_+b) * G_ * I_];
    float acc[8][8];
    #pragma unroll
    for (int i = 0; i < 8; i++)
        #pragma unroll
        for (int j = 0; j < 8; j++) acc[i][j] = 0.f;
    int tx = tid & 15, ty = tid >> 4;
    for (int kc = 0; kc < I_; kc += 16) {
        #pragma unroll
        for (int u = 0; u < 2; u++) {
            int e = tid + u*256, row = e >> 2, c4 = e & 3;
            float4 v = *(const float4*)&A[(size_t)(t0+row)*I_ + kc + c4*4];
            As[c4*4+0][row]=v.x; As[c4*4+1][row]=v.y; As[c4*4+2][row]=v.z; As[c4*4+3][row]=v.w;
            float4 w = *(const float4*)&Bw[(size_t)(g0+row)*I_ + kc + c4*4];
            Bs[c4*4+0][row]=w.x; Bs[c4*4+1][row]=w.y; Bs[c4*4+2][row]=w.z; Bs[c4*4+3][row]=w.w;
        }
        __syncthreads();
        #pragma unroll
        for (int kk = 0; kk < 16; kk++) {
            float4 a0 = *(float4*)&As[kk][tx*8];
            float4 a1 = *(float4*)&As[kk][tx*8+4];
            float4 b0 = *(float4*)&Bs[kk][ty*8];
            float4 b1 = *(float4*)&Bs[kk][ty*8+4];
            float av[8] = {a0.x,a0.y,a0.z,a0.w,a1.x,a1.y,a1.z,a1.w};
            float bv[8] = {b0.x,b0.y,b0.z,b0.w,b1.x,b1.y,b1.z,b1.w};
            #pragma unroll
            for (int i = 0; i < 8; i++)
                #pragma unroll
                for (int j = 0; j < 8; j++) acc[i][j] += av[i]*bv[j];
        }
        __syncthreads();
    }
    const float* bm = &g_bmix[((d*B_+b) << 11) + g0 + ty*8];
    float bj[8];
    #pragma unroll
    for (int j = 0; j < 8; j++) bj[j] = bm[j];
    float* O = &g_gatesx[(size_t)(d*B_+b) * T_ * G_];
    #pragma unroll
    for (int i = 0; i < 8; i++) {
        int t = t0 + tx*8 + i;
        #pragma unroll
        for (int j = 0; j < 8; j += 4) {
            float4 v = make_float4(acc[i][j]+bj[j], acc[i][j+1]+bj[j+1],
                                   acc[i][j+2]+bj[j+2], acc[i][j+3]+bj[j+3]);
            *(float4*)&O[(size_t)t*G_ + g0 + ty*8 + j] = v;
        }
    }
}

// ---------------- K7: persistent tensor-core recurrence (all 256 steps) ----------------
#define CP16(dst, src) asm volatile("cp.async.ca.shared.global [%0], [%1], 16;\n"::"r"(dst),"l"(src):"memory")
#define LDX4(r0,r1,r2,r3,ad) asm volatile("ldmatrix.sync.aligned.m8n8.x4.shared.b16 {%0,%1,%2,%3}, [%4];":"=r"(r0),"=r"(r1),"=r"(r2),"=r"(r3):"r"(ad))
#define MMA16(cc,a0,a1,a2,a3,b0,b1) asm volatile( \
    "mma.sync.aligned.m16n8k16.row.col.f32.f16.f16.f32 {%0,%1,%2,%3},{%4,%5,%6,%7},{%8,%9},{%0,%1,%2,%3};" \
    :"+f"(cc[0]),"+f"(cc[1]),"+f"(cc[2]),"+f"(cc[3]) \
    :"r"(a0),"r"(a1),"r"(a2),"r"(a3),"r"(b0),"r"(b1))

// dyn smem: 3 stages x 16KB (Ah|Al|Wh|Wl, each 32x64 half, rows=128B, 8 granule swizzle)
// + 8KB float gsm[2][32][32] at offset 49152.  Total 57344.
__global__ void __launch_bounds__(256, 1) k_steps(float* __restrict__ out)
{
    extern __shared__ __align__(1024) __half smd[];
    const int tid = threadIdx.x;
    const int d  = blockIdx.x >> 6;
    const int c0 = (blockIdx.x & 63) * 8;
    const unsigned smb = (unsigned)__cvta_generic_to_shared(smd);
    float* gsm = (float*)((char*)smd + 49152);

    // --- producer mapping (R11): tile = tid>>6, 4 x 16B lines / thread ---
    const int ldt  = tid >> 6;
    const int lsub = tid & 63;
    const int lrow = lsub >> 1;
    const int li0  = (lsub & 1) * 4;
    const int r7 = lrow & 7;
    const __half* gbW = 0; const __half* gbA0 = 0; const __half* gbA1 = 0;
    if (ldt >= 2) {
        int grow = (lrow >> 3)*512 + c0 + (lrow & 7);
        gbW = ((ldt == 2) ? g_Whi : g_Wlo) + ((size_t)(d*G_ + grow))*KK_;
    } else {
        const __half* base = (ldt == 0) ? g_Ah : g_Al;
        gbA0 = base + ((size_t)((0*2+d)*B_ + lrow))*KK_;
        gbA1 = base + ((size_t)((1*2+d)*B_ + lrow))*KK_;
    }
    const unsigned dstb = smb + ldt*4096 + lrow*128;
    const unsigned dd0 = dstb + ((unsigned)((li0+0) ^ r7) << 4);
    const unsigned dd1 = dstb + ((unsigned)((li0+1) ^ r7) << 4);
    const unsigned dd2 = dstb + ((unsigned)((li0+2) ^ r7) << 4);
    const unsigned dd3 = dstb + ((unsigned)((li0+3) ^ r7) << 4);

    // --- consumer mapping: 8 warps = K-half x n16 x m16 ---
    const int lane = tid & 31, wid = tid >> 5;
    const int kh = wid & 1, nh = (wid >> 1) & 1, mh = wid >> 2;
    const int rowA = mh*16 + (lane & 15), cgA = lane >> 4;
    const int rowB = nh*16 + (lane & 15), cgB = lane >> 4;
    const int rA7 = rowA & 7, rB7 = rowB & 7;
    const unsigned baseA = smb + rowA*128;
    const unsigned baseB = smb + 8192u + rowB*128;
    const int pb = tid >> 3, pce = tid & 7;           // pointwise mapping

    for (int s = 0; s < T_; s++) {
        const int p = s & 1;
        const int t = d ? (T_-1-s) : s;
        const __half* gb = (ldt >= 2) ? gbW : (p ? gbA1 : gbA0);

#define ISSUE(c) { unsigned so = (unsigned)((c)%3)*16384u; const __half* gp = gb + (size_t)(c)*64 + li0*8; \
    CP16(dd0+so, gp); CP16(dd1+so, gp+8); CP16(dd2+so, gp+16); CP16(dd3+so, gp+24); \
    asm volatile("cp.async.commit_group;\n":::"memory"); }

        float aM0[4] = {0,0,0,0}, aM1[4] = {0,0,0,0};
        float aL0[4] = {0,0,0,0}, aL1[4] = {0,0,0,0};

        ISSUE(0); ISSUE(1);
        for (int c = 0; c < 64; c++) {
            if (c < 63) asm volatile("cp.async.wait_group 1;\n":::"memory");
            else        asm volatile("cp.async.wait_group 0;\n":::"memory");
            __syncthreads();
            if (c + 2 < 64) ISSUE(c + 2);
            unsigned st = (unsigned)(c % 3) * 16384u;
            #pragma unroll
            for (int ks = 0; ks < 2; ks++) {
                int ka = kh*2 + ks;
                unsigned offA = baseA + st + ((unsigned)((ka*2+cgA) ^ rA7) << 4);
                unsigned offB = baseB + st + ((unsigned)((ka*2+cgB) ^ rB7) << 4);
                unsigned ah0,ah1,ah2,ah3, al0,al1,al2,al3;
                unsigned bh0,bh1,bh2,bh3, bl0,bl1,bl2,bl3;
                LDX4(ah0,ah1,ah2,ah3, offA);
                LDX4(al0,al1,al2,al3, offA + 4096u);
                LDX4(bh0,bh1,bh2,bh3, offB);
                LDX4(bl0,bl1,bl2,bl3, offB + 4096u);
                MMA16(aM0, ah0,ah1,ah2,ah3, bh0,bh2);
                MMA16(aM1, ah0,ah1,ah2,ah3, bh1,bh3);
                MMA16(aL0, ah0,ah1,ah2,ah3, bl0,bl2);
                MMA16(aL1, ah0,ah1,ah2,ah3, bl1,bl3);
                MMA16(aL0, al0,al1,al2,al3, bh0,bh2);
                MMA16(aL1, al0,al1,al2,al3, bh1,bh3);
            }
        }
        __syncthreads();

        // --- stage partial gates: gsm[kh][n][m] ---
        {
            int r = lane >> 2, cn = (lane & 3) * 2;
            int nb0 = nh*16, m0 = mh*16;
            float* gk = gsm + kh*1024;
            gk[(nb0+cn  )*32 + m0+r  ] = aM0[0] + aL0[0]*LOIN;
            gk[(nb0+cn+1)*32 + m0+r  ] = aM0[1] + aL0[1]*LOIN;
            gk[(nb0+cn  )*32 + m0+r+8] = aM0[2] + aL0[2]*LOIN;
            gk[(nb0+cn+1)*32 + m0+r+8] = aM0[3] + aL0[3]*LOIN;
            gk[(nb0+8+cn  )*32 + m0+r  ] = aM1[0] + aL1[0]*LOIN;
            gk[(nb0+8+cn+1)*32 + m0+r  ] = aM1[1] + aL1[1]*LOIN;
            gk[(nb0+8+cn  )*32 + m0+r+8] = aM1[2] + aL1[2]*LOIN;
            gk[(nb0+8+cn+1)*32 + m0+r+8] = aM1[3] + aL1[3]*LOIN;
        }
        __syncthreads();

        // --- LSTM pointwise + next-step H~ staging ---
        {
            int b = pb, ce = pce;
            const float* gx = g_gatesx + ((size_t)(d*B_+b)*T_ + t)*G_ + c0 + ce;
            float gi = gsm[(ce   )*32 + b] + gsm[1024 + (ce   )*32 + b] + gx[0];
            float gf = gsm[(8+ce )*32 + b] + gsm[1024 + (8+ce )*32 + b] + gx[512];
            float gg = gsm[(16+ce)*32 + b] + gsm[1024 + (16+ce)*32 + b] + gx[1024];
            float go = gsm[(24+ce)*32 + b] + gsm[1024 + (24+ce)*32 + b] + gx[1536];
            int cell = c0 + ce;
            float cprev = g_cst[(d*B_+b)*C_ + cell];
            float i_ = 1.f / (1.f + expf(-gi));
            float f_ = 1.f / (1.f + expf(-gf));
            float g2 = tanhf(gg);
            float o_ = 1.f / (1.f + expf(-go));
            float cy = f_*cprev + i_*g2;
            float hy = o_*tanhf(cy);
            int len = g_len[b];
            bool valid = d ? ((T_ - s) <= len) : (s < len);
            if (!valid) { cy = 0.f; hy = 0.f; }
            g_cst[(d*B_+b)*C_ + cell] = cy;
            out[((size_t)b*T_ + t)*(2*C_) + d*C_ + cell] = hy;
            int pn = p ^ 1;
            size_t ab = ((size_t)((pn*2+d)*B_ + b))*KK_ + cell;
            #pragma unroll
            for (int n = 0; n < 8; n++) {
                float af = g_cb[b*8+n] * hy;
                __half h = __float2half(af);
                g_Ah[ab + n*512] = h;
                g_Al[ab + n*512] = __float2half((af - __half2float(h)) * LOSC);
            }
        }

        // --- grid barrier (release writes, acquire before next step's reads) ---
        __syncthreads();
        if (tid == 0) {
            __threadfence();
            atomicAdd(&g_bar, 1);
            int target = GRID_STEP * (s + 1);
            while (*(volatile int*)&g_bar < target) { }
            __threadfence();
        }
        __syncthreads();
    }
}

// ---------------- launcher ----------------
extern "C" void kernel_launch(void* const* d_in, const int* in_sizes, int n_in,
                              void* d_out, int out_size)
{
    const float* x    = (const float*)d_in[0];
    const void*  mask = (const void*)d_in[1];
    const int*   ma   = (const int*)d_in[2];
    const int*   mc   = (const int*)d_in[3];
    const float* EA   = (const float*)d_in[4];
    const float* EC   = (const float*)d_in[5];
    const float* W1   = (const float*)d_in[6];
    const float* b1   = (const float*)d_in[7];
    const float* W2   = (const float*)d_in[8];
    const float* Wih  = (const float*)d_in[9];
    const float* Whh  = (const float*)d_in[10];
    const float* bias = (const float*)d_in[11];
    const float* WihR = (const float*)d_in[12];
    const float* WhhR = (const float*)d_in[13];
    const float* biasR= (const float*)d_in[14];
    float*       out  = (float*)d_out;

    cudaFuncSetAttribute(k_steps, cudaFuncAttributeMaxDynamicSharedMemorySize, 57344);

    k_prep   <<<B_, 32>>>(mask, ma, mc, EA, EC, W1, b1, W2);
    k_init   <<<1024, 256>>>();
    k_mixbias<<<512, 256>>>(bias, biasR);
    k_mix_ih <<<2048, 256>>>(Wih, WihR);
    k_wcvt   <<<8192, 256>>>(Whh, WhhR);
    k_ingemm <<<2048, 256>>>(x);
    k_steps  <<<GRID_STEP, 256, 57344>>>(out);
}

// round 17
// speedup vs baseline: 2.0693x; 1.3117x over previous
#include <cuda_runtime.h>
#include <cuda_fp16.h>
#include <math.h>

#define B_   32
#define T_   256
#define I_   512
#define C_   512
#define G_   2048
#define NB_  8
#define KK_  4096
#define LOSC 2048.0f
#define LOIN (1.0f/2048.0f)
#define GRID_STEP 128

// ---------------- scratch ----------------
__device__ float  g_cb[B_ * NB_];
__device__ int    g_len[B_];
__device__ float  g_bmix[2 * B_ * G_];
__device__ float  g_WihMix[2UL * B_ * G_ * I_];
__device__ float  g_gatesx[2UL * B_ * T_ * G_];
__device__ __half g_Whi[2UL * G_ * KK_];             // [d][g][n*512+k] hi
__device__ __half g_Wlo[2UL * G_ * KK_];             // lo * 2^11
__device__ __half g_Ah[2 * 2 * B_ * C_];             // h hi [parity][d][b][k]  (NOT c-scaled)
__device__ __half g_Al[2 * 2 * B_ * C_];             // h lo * 2^11
__device__ float  g_cst[2 * B_ * C_];
__device__ int    g_bar;

// ---------------- K1: lengths + c_batch ----------------
__global__ void k_prep(const void* __restrict__ mask_raw,
                       const int* __restrict__ ma, const int* __restrict__ mc,
                       const float* __restrict__ EA, const float* __restrict__ EC,
                       const float* __restrict__ W1, const float* __restrict__ b1,
                       const float* __restrict__ W2)
{
    __shared__ float q[128], hid[64], lg[8];
    int b = blockIdx.x, lane = threadIdx.x;
    int w0 = ((const int*)mask_raw)[0];
    int mode = (w0 == 1) ? 1 : ((w0 == 0x3F800000) ? 2 : 0);
    int s = 0;
    if (mode == 1) { const int* m = (const int*)mask_raw;
        for (int t = lane; t < T_; t += 32) s += (m[b*T_+t] != 0);
    } else if (mode == 2) { const float* m = (const float*)mask_raw;
        for (int t = lane; t < T_; t += 32) s += (m[b*T_+t] != 0.0f);
    } else { const unsigned char* m = (const unsigned char*)mask_raw;
        for (int t = lane; t < T_; t += 32) s += (m[b*T_+t] != 0);
    }
    #pragma unroll
    for (int o = 16; o; o >>= 1) s += __shfl_xor_sync(0xffffffffu, s, o);
    if (lane == 0) g_len[b] = s;

    int a = ma[b], c = mc[b];
    #pragma unroll
    for (int u = 0; u < 4; u++) {
        int i = lane*4 + u;
        q[i] = (i < 64) ? EA[a*64 + i] : EC[c*64 + (i-64)];
    }
    __syncwarp();
    for (int j = lane; j < 64; j += 32) {
        float acc = b1[j];
        for (int i = 0; i < 128; i++) acc += q[i] * W1[i*64 + j];
        hid[j] = tanhf(acc);
    }
    __syncwarp();
    if (lane < 8) {
        float acc = 0.f;
        for (int j = 0; j < 64; j++) acc += hid[j] * W2[j*8 + lane];
        lg[lane] = acc;
    }
    __syncwarp();
    if (lane < 8) {
        float m = lg[0];
        #pragma unroll
        for (int n = 1; n < 8; n++) m = fmaxf(m, lg[n]);
        float Z = 0.f;
        #pragma unroll
        for (int n = 0; n < 8; n++) Z += expf(lg[n] - m);
        g_cb[b*8 + lane] = expf(lg[lane] - m) / Z;
    }
}

// ---------------- K2: zero h buffers + c state + barrier ----------------
__global__ void k_init()
{
    int i = blockIdx.x * 256 + threadIdx.x;           // 32768 threads
    ((unsigned int*)g_Ah)[i] = 0u;                    // 65536 halves = 32768 u32
    ((unsigned int*)g_Al)[i] = 0u;
    g_cst[i] = 0.f;                                   // 32768 floats
    if (i == 0) g_bar = 0;
}

// ---------------- K3: mixed bias ----------------
__global__ void k_mixbias(const float* __restrict__ bf, const float* __restrict__ br)
{
    int idx = blockIdx.x * 256 + threadIdx.x;
    int g = idx & (G_-1), b = (idx >> 11) & 31, d = idx >> 16;
    const float* bias = d ? br : bf;
    float acc = 0.f;
    #pragma unroll
    for (int n = 0; n < NB_; n++) acc += g_cb[b*8+n] * bias[n*G_ + g];
    g_bmix[idx] = acc;
}

// ---------------- K4: mix input weights ----------------
__global__ void k_mix_ih(const float* __restrict__ Wf, const float* __restrict__ Wr)
{
    __shared__ float cbs[256];
    int tid = threadIdx.x;
    cbs[tid] = g_cb[tid];
    __syncthreads();
    int idx = blockIdx.x * 256 + tid;
    int k4 = idx & 127, g = (idx >> 7) & (G_-1), d = idx >> 18;
    const float* W = d ? Wr : Wf;
    float4 w[NB_];
    #pragma unroll
    for (int n = 0; n < NB_; n++)
        w[n] = *(const float4*)&W[((size_t)n*G_ + g)*I_ + k4*4];
    for (int b = 0; b < B_; b++) {
        float4 o = make_float4(0.f,0.f,0.f,0.f);
        #pragma unroll
        for (int n = 0; n < NB_; n++) {
            float c = cbs[b*8+n];
            o.x += c*w[n].x; o.y += c*w[n].y; o.z += c*w[n].z; o.w += c*w[n].w;
        }
        *(float4*)&g_WihMix[((size_t)(d*B_+b)*G_ + g)*I_ + k4*4] = o;
    }
}

// ---------------- K5: basis Whh -> fp16 hi/lo, layout [d][g][n*512+k] ----------------
__global__ void k_wcvt(const float* __restrict__ Wf, const float* __restrict__ Wr)
{
    int idx = blockIdx.x * 256 + threadIdx.x;
    int k8 = idx & 63, n = (idx >> 6) & 7, g = (idx >> 9) & 2047, d = idx >> 20;
    const float* W = d ? Wr : Wf;
    const float* src = &W[((size_t)n*G_ + g)*C_ + k8*8];
    float4 v0 = *(const float4*)src;
    float4 v1 = *(const float4*)(src + 4);
    float vs[8] = {v0.x,v0.y,v0.z,v0.w, v1.x,v1.y,v1.z,v1.w};
    __half h8[8], l8[8];
    #pragma unroll
    for (int i = 0; i < 8; i++) {
        __half h = __float2half(vs[i]);
        h8[i] = h;
        l8[i] = __float2half((vs[i] - __half2float(h)) * LOSC);
    }
    size_t dst = (size_t)(d*G_ + g)*KK_ + n*C_ + k8*8;
    *(uint4*)(g_Whi + dst) = *(uint4*)h8;
    *(uint4*)(g_Wlo + dst) = *(uint4*)l8;
}

// ---------------- K6: input GEMM + bias fold ----------------
__global__ void __launch_bounds__(256, 2) k_ingemm(const float* __restrict__ x)
{
    __shared__ float As[16][132];
    __shared__ float Bs[16][132];
    int tid = threadIdx.x;
    int gt = blockIdx.x & 15, tt = (blockIdx.x >> 4) & 1;
    int b = (blockIdx.x >> 5) & 31, d = blockIdx.x >> 10;
    int t0 = tt*128, g0 = gt*128;
    const float* A  = &x[(size_t)b * T_ * I_];
    const float* Bw = &g_WihMix[(size_t)(d*B_+b) * G_ * I_];
    float acc[8][8];
    #pragma unroll
    for (int i = 0; i < 8; i++)
        #pragma unroll
        for (int j = 0; j < 8; j++) acc[i][j] = 0.f;
    int tx = tid & 15, ty = tid >> 4;
    for (int kc = 0; kc < I_; kc += 16) {
        #pragma unroll
        for (int u = 0; u < 2; u++) {
            int e = tid + u*256, row = e >> 2, c4 = e & 3;
            float4 v = *(const float4*)&A[(size_t)(t0+row)*I_ + kc + c4*4];
            As[c4*4+0][row]=v.x; As[c4*4+1][row]=v.y; As[c4*4+2][row]=v.z; As[c4*4+3][row]=v.w;
            float4 w = *(const float4*)&Bw[(size_t)(g0+row)*I_ + kc + c4*4];
            Bs[c4*4+0][row]=w.x; Bs[c4*4+1][row]=w.y; Bs[c4*4+2][row]=w.z; Bs[c4*4+3][row]=w.w;
        }
        __syncthreads();
        #pragma unroll
        for (int kk = 0; kk < 16; kk++) {
            float4 a0 = *(float4*)&As[kk][tx*8];
            float4 a1 = *(float4*)&As[kk][tx*8+4];
            float4 b0 = *(float4*)&Bs[kk][ty*8];
            float4 b1 = *(float4*)&Bs[kk][ty*8+4];
            float av[8] = {a0.x,a0.y,a0.z,a0.w,a1.x,a1.y,a1.z,a1.w};
            float bv[8] = {b0.x,b0.y,b0.z,b0.w,b1.x,b1.y,b1.z,b1.w};
            #pragma unroll
            for (int i = 0; i < 8; i++)
                #pragma unroll
                for (int j = 0; j < 8; j++) acc[i][j] += av[i]*bv[j];
        }
        __syncthreads();
    }
    const float* bm = &g_bmix[((d*B_+b) << 11) + g0 + ty*8];
    float bj[8];
    #pragma unroll
    for (int j = 0; j < 8; j++) bj[j] = bm[j];
    float* O = &g_gatesx[(size_t)(d*B_+b) * T_ * G_];
    #pragma unroll
    for (int i = 0; i < 8; i++) {
        int t = t0 + tx*8 + i;
        #pragma unroll
        for (int j = 0; j < 8; j += 4) {
            float4 v = make_float4(acc[i][j]+bj[j], acc[i][j+1]+bj[j+1],
                                   acc[i][j+2]+bj[j+2], acc[i][j+3]+bj[j+3]);
            *(float4*)&O[(size_t)t*G_ + g0 + ty*8 + j] = v;
        }
    }
}

// ---------------- K7: persistent recurrence, basis-mix in epilogue ----------------
#define CP16(dst, src) asm volatile("cp.async.ca.shared.global [%0], [%1], 16;\n"::"r"(dst),"l"(src):"memory")
#define CPCOMMIT() asm volatile("cp.async.commit_group;\n":::"memory")
#define LDX4(r0,r1,r2,r3,ad) asm volatile("ldmatrix.sync.aligned.m8n8.x4.shared.b16 {%0,%1,%2,%3}, [%4];":"=r"(r0),"=r"(r1),"=r"(r2),"=r"(r3):"r"(ad))
#define MMA16(cc,a0,a1,a2,a3,b0,b1) asm volatile( \
    "mma.sync.aligned.m16n8k16.row.col.f32.f16.f16.f32 {%0,%1,%2,%3},{%4,%5,%6,%7},{%8,%9},{%0,%1,%2,%3};" \
    :"+f"(cc[0]),"+f"(cc[1]),"+f"(cc[2]),"+f"(cc[3]) \
    :"r"(a0),"r"(a1),"r"(a2),"r"(a3),"r"(b0),"r"(b1))

// dyn smem: A [8 sub][hi/lo][32][64] = 64KB @0; W stages 3x[hi/lo][32][64]=24KB @65536;
// gsm float[4][32][32]=16KB @90112; cbs float[256]=1KB @106496. Total 107520.
__global__ void __launch_bounds__(256, 1) k_steps(float* __restrict__ out)
{
    extern __shared__ __align__(1024) char smd[];
    const int tid = threadIdx.x;
    const int d  = blockIdx.x >> 6;
    const int c0 = (blockIdx.x & 63) * 8;
    const unsigned smb = (unsigned)__cvta_generic_to_shared(smd);
    float* gsm = (float*)(smd + 90112);
    float* cbs = (float*)(smd + 106496);

    if (tid < 256) cbs[tid] = g_cb[tid];

    // --- W producer mapping: 2 x 16B per thread per chunk ---
    const int whl  = tid >> 7;
    const int widx = tid & 127;
    const int wrow = widx >> 2;
    const int wgp  = (widx & 3) * 2;
    const int wr7  = wrow & 7;
    const __half* gbW = ((whl) ? g_Wlo : g_Whi)
        + ((size_t)(d*G_ + ((wrow >> 3)*512 + c0 + (wrow & 7))))*KK_;
    const unsigned wd0 = smb + whl*4096 + wrow*128 + ((unsigned)((wgp  ) ^ wr7) << 4);
    const unsigned wd1 = smb + whl*4096 + wrow*128 + ((unsigned)((wgp+1) ^ wr7) << 4);
#define ISSUEW(c) { unsigned so = 65536u + ((unsigned)((c)%3))*8192u; \
    const __half* gp = gbW + (size_t)(c)*64 + wgp*8; \
    CP16(wd0+so, gp); CP16(wd1+so, gp+8); CPCOMMIT(); }

    // --- A producer mapping: warp w loads sub-chunk w (8KB), 16 x 16B per lane ---
    const int lane = tid & 31, wid = tid >> 5;
    const int aw  = wid;
    const int hlA = lane >> 4;
    const int lx  = lane & 15;
    const __half* aS0h = g_Ah + (size_t)((0*2+d)*B_)*512;
    const __half* aS1h = g_Ah + (size_t)((1*2+d)*B_)*512;
    const __half* aS0l = g_Al + (size_t)((0*2+d)*B_)*512;
    const __half* aS1l = g_Al + (size_t)((1*2+d)*B_)*512;

    // --- consumer mapping: 8 warps = kh(4) x mh(2); n32 per warp ---
    const int kh = wid & 3, mh = wid >> 2;
    const int rowA = mh*16 + (lane & 15), cgA = lane >> 4;
    const int rB   = lane & 15,           cgB = lane >> 4;
    const int rA7 = rowA & 7, rB7 = rB & 7;
    const unsigned aoffb = (unsigned)rowA*128 + ((unsigned)((kh*2+cgA) ^ rA7) << 4);
    const unsigned boff0 = (unsigned)rB*128 + ((unsigned)((kh*2+cgB) ^ rB7) << 4);
    const unsigned boff1 = boff0 + 16*128;
    const int crow = mh*16 + (lane >> 2);             // accum row (and +8)
    const int pb = tid >> 3, pce = tid & 7;

    for (int s = 0; s < T_; s++) {
        const int p = s & 1;
        const int t = d ? (T_-1-s) : s;

        // A preload (one commit group)
        {
            const __half* aS = hlA ? (p ? aS1l : aS0l) : (p ? aS1h : aS0h);
            #pragma unroll
            for (int rr = 0; rr < 2; rr++) {
                int row = lx*2 + rr;
                const __half* sp = aS + row*512 + aw*64;
                unsigned dst = smb + aw*8192 + hlA*4096 + row*128;
                int r7 = row & 7;
                #pragma unroll
                for (int g = 0; g < 8; g++)
                    CP16(dst + ((unsigned)(g ^ r7) << 4), sp + g*8);
            }
            CPCOMMIT();
        }
        ISSUEW(0); ISSUEW(1);

        float aM[4][4], aL[4][4], tM[4][4], tL[4][4];
        #pragma unroll
        for (int f = 0; f < 4; f++)
            #pragma unroll
            for (int j = 0; j < 4; j++) { aM[f][j]=0.f; aL[f][j]=0.f; tM[f][j]=0.f; tL[f][j]=0.f; }

        for (int c = 0; c < 64; c++) {
            if (c < 63) asm volatile("cp.async.wait_group 1;\n":::"memory");
            else        asm volatile("cp.async.wait_group 0;\n":::"memory");
            __syncthreads();
            if (c + 2 < 64) ISSUEW(c + 2);

            unsigned aoff = smb + (unsigned)(c & 7)*8192u + aoffb;
            unsigned so   = smb + 65536u + ((unsigned)(c % 3))*8192u;
            unsigned ah0,ah1,ah2,ah3, al0,al1,al2,al3;
            unsigned bh0,bh1,bh2,bh3, bh4,bh5,bh6,bh7;
            unsigned bl0,bl1,bl2,bl3, bl4,bl5,bl6,bl7;
            LDX4(ah0,ah1,ah2,ah3, aoff);
            LDX4(al0,al1,al2,al3, aoff + 4096u);
            LDX4(bh0,bh1,bh2,bh3, so + boff0);
            LDX4(bh4,bh5,bh6,bh7, so + boff1);
            LDX4(bl0,bl1,bl2,bl3, so + boff0 + 4096u);
            LDX4(bl4,bl5,bl6,bl7, so + boff1 + 4096u);

            MMA16(aM[0], ah0,ah1,ah2,ah3, bh0,bh2);
            MMA16(aM[1], ah0,ah1,ah2,ah3, bh1,bh3);
            MMA16(aM[2], ah0,ah1,ah2,ah3, bh4,bh6);
            MMA16(aM[3], ah0,ah1,ah2,ah3, bh5,bh7);
            MMA16(aL[0], ah0,ah1,ah2,ah3, bl0,bl2);
            MMA16(aL[1], ah0,ah1,ah2,ah3, bl1,bl3);
            MMA16(aL[2], ah0,ah1,ah2,ah3, bl4,bl6);
            MMA16(aL[3], ah0,ah1,ah2,ah3, bl5,bl7);
            MMA16(aL[0], al0,al1,al2,al3, bh0,bh2);
            MMA16(aL[1], al0,al1,al2,al3, bh1,bh3);
            MMA16(aL[2], al0,al1,al2,al3, bh4,bh6);
            MMA16(aL[3], al0,al1,al2,al3, bh5,bh7);

            if ((c & 7) == 7) {                       // basis boundary: mix into totals
                int n = c >> 3;
                float c0v = cbs[crow*8 + n];
                float c1v = cbs[(crow+8)*8 + n];
                #pragma unroll
                for (int f = 0; f < 4; f++) {
                    tM[f][0] += c0v*aM[f][0]; tM[f][1] += c0v*aM[f][1];
                    tM[f][2] += c1v*aM[f][2]; tM[f][3] += c1v*aM[f][3];
                    tL[f][0] += c0v*aL[f][0]; tL[f][1] += c0v*aL[f][1];
                    tL[f][2] += c1v*aL[f][2]; tL[f][3] += c1v*aL[f][3];
                    #pragma unroll
                    for (int j = 0; j < 4; j++) { aM[f][j]=0.f; aL[f][j]=0.f; }
                }
            }
        }

        // --- stage K-split partials: gsm[kh][n][m] ---
        {
            int r = lane >> 2, cn = (lane & 3) * 2;
            #pragma unroll
            for (int f = 0; f < 4; f++) {
                int nb = f*8;
                gsm[kh*1024 + (nb+cn  )*32 + mh*16 + r    ] = tM[f][0] + tL[f][0]*LOIN;
                gsm[kh*1024 + (nb+cn+1)*32 + mh*16 + r    ] = tM[f][1] + tL[f][1]*LOIN;
                gsm[kh*1024 + (nb+cn  )*32 + mh*16 + r + 8] = tM[f][2] + tL[f][2]*LOIN;
                gsm[kh*1024 + (nb+cn+1)*32 + mh*16 + r + 8] = tM[f][3] + tL[f][3]*LOIN;
            }
        }
        __syncthreads();

        // --- LSTM pointwise + next-step h staging ---
        {
            int b = pb, ce = pce;
            const float* gx = g_gatesx + ((size_t)(d*B_+b)*T_ + t)*G_ + c0 + ce;
            float gi = gsm[(ce   )*32+b] + gsm[1024+(ce   )*32+b] + gsm[2048+(ce   )*32+b] + gsm[3072+(ce   )*32+b] + gx[0];
            float gf = gsm[(8+ce )*32+b] + gsm[1024+(8+ce )*32+b] + gsm[2048+(8+ce )*32+b] + gsm[3072+(8+ce )*32+b] + gx[512];
            float gg = gsm[(16+ce)*32+b] + gsm[1024+(16+ce)*32+b] + gsm[2048+(16+ce)*32+b] + gsm[3072+(16+ce)*32+b] + gx[1024];
            float go = gsm[(24+ce)*32+b] + gsm[1024+(24+ce)*32+b] + gsm[2048+(24+ce)*32+b] + gsm[3072+(24+ce)*32+b] + gx[1536];
            int cell = c0 + ce;
            float cprev = g_cst[(d*B_+b)*C_ + cell];
            float i_ = 1.f / (1.f + expf(-gi));
            float f_ = 1.f / (1.f + expf(-gf));
            float g2 = tanhf(gg);
            float o_ = 1.f / (1.f + expf(-go));
            float cy = f_*cprev + i_*g2;
            float hy = o_*tanhf(cy);
            int len = g_len[b];
            bool valid = d ? ((T_ - s) <= len) : (s < len);
            if (!valid) { cy = 0.f; hy = 0.f; }
            g_cst[(d*B_+b)*C_ + cell] = cy;
            out[((size_t)b*T_ + t)*(2*C_) + d*C_ + cell] = hy;
            int pn = p ^ 1;
            size_t ab = ((size_t)((pn*2+d)*B_ + b))*512 + cell;
            __half h = __float2half(hy);
            g_Ah[ab] = h;
            g_Al[ab] = __float2half((hy - __half2float(h)) * LOSC);
        }

        // --- grid barrier ---
        __syncthreads();
        if (tid == 0) {
            __threadfence();
            atomicAdd(&g_bar, 1);
            int target = GRID_STEP * (s + 1);
            while (*(volatile int*)&g_bar < target) { }
            __threadfence();
        }
        __syncthreads();
    }
}

// ---------------- launcher ----------------
extern "C" void kernel_launch(void* const* d_in, const int* in_sizes, int n_in,
                              void* d_out, int out_size)
{
    const float* x    = (const float*)d_in[0];
    const void*  mask = (const void*)d_in[1];
    const int*   ma   = (const int*)d_in[2];
    const int*   mc   = (const int*)d_in[3];
    const float* EA   = (const float*)d_in[4];
    const float* EC   = (const float*)d_in[5];
    const float* W1   = (const float*)d_in[6];
    const float* b1   = (const float*)d_in[7];
    const float* W2   = (const float*)d_in[8];
    const float* Wih  = (const float*)d_in[9];
    const float* Whh  = (const float*)d_in[10];
    const float* bias = (const float*)d_in[11];
    const float* WihR = (const float*)d_in[12];
    const float* WhhR = (const float*)d_in[13];
    const float* biasR= (const float*)d_in[14];
    float*       out  = (float*)d_out;

    cudaFuncSetAttribute(k_steps, cudaFuncAttributeMaxDynamicSharedMemorySize, 107520);

    k_prep   <<<B_, 32>>>(mask, ma, mc, EA, EC, W1, b1, W2);
    k_init   <<<128, 256>>>();
    k_mixbias<<<512, 256>>>(bias, biasR);
    k_mix_ih <<<2048, 256>>>(Wih, WihR);
    k_wcvt   <<<8192, 256>>>(Whh, WhhR);
    k_ingemm <<<2048, 256>>>(x);
    k_steps  <<<GRID_STEP, 256, 107520>>>(out);
}